// round 17
// baseline (speedup 1.0000x reference)
#include <cuda_runtime.h>

// LSTM_584115552367: B=65536 independent LSTMs, D=H=17, T=50, SLB=30.
// R15: R14 core (best, 526.1us) +
//  - teacher ih-matvec hoisted OUT of the recurrence: XW[t,g,b] =
//    s(g)*(x@Wih_m^T + b) precomputed by a fully-parallel kernel into a
//    [t][g][b] scratch (coalesced writes AND reads). Teacher step becomes
//    gates = xw + h@Whh: half the fma2 + half the loads, no staging syncs
//    (private SMEM rows, same-thread STS->LDS needs no barrier).
//  - all gate weights pre-scaled by -log2e (i,f,o) / -2log2e (g): every
//    sigmoid/tanh loses its leading FMUL.
//  - ports: Whh/Wcomb (i,f) -> SMEM LDS, (g,o) -> constant LDC; lin -> LDC.

#define BSZ   65536
#define TLEN  50
#define DDIM  17
#define SLBC  30
#define NP    9            // padded d-pairs (18/2)
#define TPB   64
#define TOUT  (TLEN - SLBC)
#define XROW  18           // out staging row stride (floats)
#define XWROW 69           // xw staging row stride (floats; 69 mod 32 = 5 -> conflict-free)

#define S1f (-1.4426950408889634f)   // i, f, o gates: sigm(z) = rcp(1+ex2(S1*z))
#define S2f (-2.8853900817779268f)   // g gate / tanh: tanh(z) = 2*rcp(1+ex2(S2*z))-1

typedef unsigned long long u64;

// constant layout (ulonglong2):
//   [0..152]   Whh (g,o) pairs, prescaled; pads 0
//   [153..305] Wcomb (g,o) pairs, prescaled; pad hi lane = prescaled bias_comb
//   [306..386] lin pairs; pad hi lane = blin (unscaled)
#define OFF_HHGO 0
#define OFF_CGO  153
#define OFF_LIN  306
#define CBUF_N   387

__device__   ulonglong2 g_wbuf[CBUF_N];
__device__   ulonglong2 g_whh_if[DDIM * NP];   // Whh (i,f), prescaled -> SMEM
__device__   ulonglong2 g_wc_if[DDIM * NP];    // Wcomb (i,f), prescaled -> SMEM
__device__   float g_xw[(long)SLBC * 68 * BSZ];  // [t][g][b] prescaled preacts incl bias
__constant__ ulonglong2 cbuf[CBUF_N];

#define CHGO(j,p)   cbuf[OFF_HHGO + (j)*NP + (p)]
#define CCGO(j,p)   cbuf[OFF_CGO  + (j)*NP + (p)]
#define CLIN(ccp,p) cbuf[OFF_LIN  + (ccp)*NP + (p)]

__device__ __forceinline__ u64 pack2(float lo, float hi) {
    u64 r; asm("mov.b64 %0, {%1, %2};" : "=l"(r) : "f"(lo), "f"(hi)); return r;
}
__device__ __forceinline__ void unpack2(u64 v, float &lo, float &hi) {
    asm("mov.b64 {%0, %1}, %2;" : "=f"(lo), "=f"(hi) : "l"(v));
}
__device__ __forceinline__ void fma2a(u64 &acc, u64 a, u64 b) {
    asm("fma.rn.f32x2 %0, %1, %2, %0;" : "+l"(acc) : "l"(a), "l"(b));
}
__device__ __forceinline__ u64 mul2(u64 a, u64 b) {
    u64 r; asm("mul.rn.f32x2 %0, %1, %2;" : "=l"(r) : "l"(a), "l"(b)); return r;
}
__device__ __forceinline__ float hadd2(u64 v) {
    float a, b; unpack2(v, a, b); return a + b;
}
__device__ __forceinline__ float ex2f(float x) {
    float r; asm("ex2.approx.f32 %0, %1;" : "=f"(r) : "f"(x)); return r;
}
__device__ __forceinline__ float rcpf(float x) {
    float r; asm("rcp.approx.f32 %0, %1;" : "=f"(r) : "f"(x)); return r;
}
// prescaled-input activations: a already = S1*z (sigm) or S2*z (tanh)
__device__ __forceinline__ float sigmP(float a) { return rcpf(1.0f + ex2f(a)); }
__device__ __forceinline__ float tanhP(float a) { return fmaf(2.0f, rcpf(1.0f + ex2f(a)), -1.0f); }
__device__ __forceinline__ float tanhN(float x) { return tanhP(S2f * x); }   // normal domain

// ---- prep: masked+prescaled Whh / Wcomb / lin tables ----
__device__ __forceinline__ float whm_(const float* W, const float* M, int g, int d) {
    return W[g * DDIM + d] * M[g * DDIM + d];
}
__global__ void prep_kernel(
    const float* __restrict__ Wih,  const float* __restrict__ Whh,
    const float* __restrict__ bih,  const float* __restrict__ bhh,
    const float* __restrict__ Wlin, const float* __restrict__ blin,
    const float* __restrict__ mih,  const float* __restrict__ mhh)
{
    int tid = threadIdx.x;   // 128 threads, 1 block
    for (int idx = tid; idx < DDIM * NP; idx += 128) {
        int j = idx / NP, p = idx % NP, d0 = 2 * p, d1 = d0 + 1;
        bool v1 = (d1 < DDIM);
        // Whh (pads 0)
        float i0 = S1f * whm_(Whh, mhh, j, d0),      i1 = v1 ? S1f * whm_(Whh, mhh, j, d1) : 0.0f;
        float f0 = S1f * whm_(Whh, mhh, 17 + j, d0), f1 = v1 ? S1f * whm_(Whh, mhh, 17 + j, d1) : 0.0f;
        float q0 = S2f * whm_(Whh, mhh, 34 + j, d0), q1 = v1 ? S2f * whm_(Whh, mhh, 34 + j, d1) : 0.0f;
        float o0 = S1f * whm_(Whh, mhh, 51 + j, d0), o1 = v1 ? S1f * whm_(Whh, mhh, 51 + j, d1) : 0.0f;
        ulonglong2 a; a.x = pack2(i0, i1); a.y = pack2(f0, f1); g_whh_if[idx] = a;
        ulonglong2 b; b.x = pack2(q0, q1); b.y = pack2(o0, o1); g_wbuf[OFF_HHGO + idx] = b;
        // Wcomb[g][k] = sum_m Wlin[m*17+k]*wihm(g,m) + whhm(g,k)
        // bias_c[g]  = sum_m blin[m]*wihm(g,m) + bih[g]+bhh[g]
        float vals[8];
        int rows[4] = {j, 17 + j, 34 + j, 51 + j};
        float scl[4] = {S1f, S1f, S2f, S1f};
#pragma unroll
        for (int s = 0; s < 4; s++) {
            int g = rows[s];
            float acc0 = whm_(Whh, mhh, g, d0);
            for (int m = 0; m < DDIM; m++)
                acc0 += Wlin[m * DDIM + d0] * whm_(Wih, mih, g, m);
            float acc1;
            if (v1) {
                acc1 = whm_(Whh, mhh, g, d1);
                for (int m = 0; m < DDIM; m++)
                    acc1 += Wlin[m * DDIM + d1] * whm_(Wih, mih, g, m);
            } else {
                acc1 = bih[g] + bhh[g];
                for (int m = 0; m < DDIM; m++)
                    acc1 += blin[m] * whm_(Wih, mih, g, m);
            }
            vals[2 * s]     = scl[s] * acc0;
            vals[2 * s + 1] = scl[s] * acc1;
        }
        ulonglong2 ci; ci.x = pack2(vals[0], vals[1]); ci.y = pack2(vals[2], vals[3]);
        ulonglong2 cg; cg.x = pack2(vals[4], vals[5]); cg.y = pack2(vals[6], vals[7]);
        g_wc_if[idx] = ci;
        g_wbuf[OFF_CGO + idx] = cg;
    }
    for (int idx = tid; idx < NP * NP; idx += 128) {
        int ccp = idx / NP, p = idx % NP;
        int c0 = 2 * ccp, c1 = 2 * ccp + 1;
        int d0 = 2 * p, d1 = 2 * p + 1;
        float x0 = Wlin[c0 * DDIM + d0];
        float x1 = (d1 < DDIM) ? Wlin[c0 * DDIM + d1] : blin[c0];
        float y0 = (c1 < DDIM) ? Wlin[c1 * DDIM + d0] : 0.0f;
        float y1 = (c1 < DDIM) ? ((d1 < DDIM) ? Wlin[c1 * DDIM + d1] : blin[c1]) : 0.0f;
        ulonglong2 v; v.x = pack2(x0, x1); v.y = pack2(y0, y1);
        g_wbuf[OFF_LIN + idx] = v;
    }
}

// ---- xw precompute: XW[t][g][b] = s(g)*(x[b,t]@Wih_m^T + bih+bhh), t<30 ----
__global__ void __launch_bounds__(TPB) xw_kernel(
    const float* __restrict__ x,   const float* __restrict__ Wih,
    const float* __restrict__ mih, const float* __restrict__ bih,
    const float* __restrict__ bhh)
{
    __shared__ ulonglong2 sWih[DDIM * NP * 2];   // (j*9+p)*2+q; prescaled; pad = s*bias
    __shared__ float sX[TPB * XROW];

    for (int idx = threadIdx.x; idx < DDIM * NP * 2; idx += TPB) {
        int j = idx / 18, r = idx % 18, p = r / 2, q = r % 2;
        int gA = q ? (34 + j) : j;        float sA = q ? S2f : S1f;
        int gB = q ? (51 + j) : (17 + j); float sB = S1f;
        int d0 = 2 * p, d1 = d0 + 1;
        float a0 = sA * whm_(Wih, mih, gA, d0);
        float a1 = (d1 < DDIM) ? sA * whm_(Wih, mih, gA, d1) : sA * (bih[gA] + bhh[gA]);
        float b0 = sB * whm_(Wih, mih, gB, d0);
        float b1 = (d1 < DDIM) ? sB * whm_(Wih, mih, gB, d1) : sB * (bih[gB] + bhh[gB]);
        ulonglong2 v; v.x = pack2(a0, a1); v.y = pack2(b0, b1);
        sWih[idx] = v;
    }
    __syncthreads();

    const int tid = threadIdx.x;
    const long bi0 = (long)blockIdx.x * TPB;
    const float* __restrict__ xg = x + bi0 * (TLEN * DDIM);
    const u64* __restrict__ sMyRow = (const u64*)(sX + tid * XROW);

#pragma unroll 1
    for (int t = 0; t < SLBC; t++) {
        __syncthreads();
#pragma unroll
        for (int k = 0; k < DDIM; k++) {
            int idx = tid + k * TPB;
            int el = idx / DDIM, d = idx % DDIM;
            sX[el * XROW + d] = xg[(long)el * (TLEN * DDIM) + t * DDIM + d];
        }
        __syncthreads();
        u64 xi[NP];
#pragma unroll
        for (int p = 0; p < 8; p++) xi[p] = sMyRow[p];
        { float lo, hi; unpack2(sMyRow[8], lo, hi); xi[8] = pack2(lo, 1.0f); }

        const long obase = (long)t * 68 * BSZ + bi0 + tid;
#pragma unroll
        for (int jj = 0; jj < 8; jj++) {
            const int j0 = 2 * jj, j1 = j0 + 1;
            u64 ai0, af0, ag0, ao0, ai1, af1, ag1, ao1;
#pragma unroll
            for (int p = 0; p < NP; p++) {
                ulonglong2 w00 = sWih[(j0 * NP + p) * 2 + 0];
                ulonglong2 w01 = sWih[(j0 * NP + p) * 2 + 1];
                ulonglong2 w10 = sWih[(j1 * NP + p) * 2 + 0];
                ulonglong2 w11 = sWih[(j1 * NP + p) * 2 + 1];
                u64 xp = xi[p];
                if (p == 0) {
                    ai0 = mul2(xp, w00.x); af0 = mul2(xp, w00.y);
                    ag0 = mul2(xp, w01.x); ao0 = mul2(xp, w01.y);
                    ai1 = mul2(xp, w10.x); af1 = mul2(xp, w10.y);
                    ag1 = mul2(xp, w11.x); ao1 = mul2(xp, w11.y);
                } else {
                    fma2a(ai0, xp, w00.x); fma2a(af0, xp, w00.y);
                    fma2a(ag0, xp, w01.x); fma2a(ao0, xp, w01.y);
                    fma2a(ai1, xp, w10.x); fma2a(af1, xp, w10.y);
                    fma2a(ag1, xp, w11.x); fma2a(ao1, xp, w11.y);
                }
            }
            g_xw[obase + (long)(j0)      * BSZ] = hadd2(ai0);
            g_xw[obase + (long)(17 + j0) * BSZ] = hadd2(af0);
            g_xw[obase + (long)(34 + j0) * BSZ] = hadd2(ag0);
            g_xw[obase + (long)(51 + j0) * BSZ] = hadd2(ao0);
            g_xw[obase + (long)(j1)      * BSZ] = hadd2(ai1);
            g_xw[obase + (long)(17 + j1) * BSZ] = hadd2(af1);
            g_xw[obase + (long)(34 + j1) * BSZ] = hadd2(ag1);
            g_xw[obase + (long)(51 + j1) * BSZ] = hadd2(ao1);
        }
        {   // tail j = 16
            const int j = 16;
            u64 ai, af, ag, ao;
#pragma unroll
            for (int p = 0; p < NP; p++) {
                ulonglong2 w0 = sWih[(j * NP + p) * 2 + 0];
                ulonglong2 w1 = sWih[(j * NP + p) * 2 + 1];
                u64 xp = xi[p];
                if (p == 0) {
                    ai = mul2(xp, w0.x); af = mul2(xp, w0.y);
                    ag = mul2(xp, w1.x); ao = mul2(xp, w1.y);
                } else {
                    fma2a(ai, xp, w0.x); fma2a(af, xp, w0.y);
                    fma2a(ag, xp, w1.x); fma2a(ao, xp, w1.y);
                }
            }
            g_xw[obase + (long)(j)      * BSZ] = hadd2(ai);
            g_xw[obase + (long)(17 + j) * BSZ] = hadd2(af);
            g_xw[obase + (long)(34 + j) * BSZ] = hadd2(ag);
            g_xw[obase + (long)(51 + j) * BSZ] = hadd2(ao);
        }
    }
}

// ---- main recurrence ----
__global__ void __launch_bounds__(TPB, 7) lstm_kernel(float* __restrict__ out)
{
    __shared__ ulonglong2 sWhhIF[DDIM * NP];
    __shared__ ulonglong2 sWcIF[DDIM * NP];
    __shared__ float sS[TPB * XWROW];   // teacher: private xw rows (stride 69);
                                        // feedback: out staging (stride 18 view)

    for (int idx = threadIdx.x; idx < DDIM * NP; idx += TPB) {
        sWhhIF[idx] = g_whh_if[idx];
        sWcIF[idx]  = g_wc_if[idx];
    }
    __syncthreads();

    const int tid = threadIdx.x;
    const long bi0 = (long)blockIdx.x * TPB;
    float* __restrict__ og = out + bi0 * (TOUT * DDIM);
    float* __restrict__ myXW = sS + tid * XWROW;

    u64 h[NP], hnew[NP];
    float c[DDIM];
#pragma unroll
    for (int p = 0; p < NP; p++) h[p] = 0ull;
    h[8] = pack2(0.0f, 1.0f);   // hi lane = 1.0 carries bias pads (Wcomb/lin)
#pragma unroll
    for (int j = 0; j < DDIM; j++) c[j] = 0.0f;

#pragma unroll 1
    for (int t = 0; t < TLEN; t++) {
        if (t < SLBC) {
            // private-row xw staging: coalesced LDG, conflict-free STS; NO syncs
            const long base = (long)t * 68 * BSZ + bi0 + tid;
#pragma unroll
            for (int g = 0; g < 68; g++)
                myXW[g] = g_xw[base + (long)g * BSZ];

            // gates = xw + h@Whh  ((i,f) LDS, (g,o) LDC)
#pragma unroll
            for (int jj = 0; jj < 8; jj++) {
                const int j0 = 2 * jj, j1 = j0 + 1;
                u64 ai0, af0, ag0, ao0, ai1, af1, ag1, ao1;
#pragma unroll
                for (int p = 0; p < NP; p++) {
                    ulonglong2 wif0 = sWhhIF[j0 * NP + p];
                    ulonglong2 wif1 = sWhhIF[j1 * NP + p];
                    ulonglong2 wgo0 = CHGO(j0, p);
                    ulonglong2 wgo1 = CHGO(j1, p);
                    u64 hp = h[p];
                    if (p == 0) {
                        ai0 = mul2(hp, wif0.x); af0 = mul2(hp, wif0.y);
                        ag0 = mul2(hp, wgo0.x); ao0 = mul2(hp, wgo0.y);
                        ai1 = mul2(hp, wif1.x); af1 = mul2(hp, wif1.y);
                        ag1 = mul2(hp, wgo1.x); ao1 = mul2(hp, wgo1.y);
                    } else {
                        fma2a(ai0, hp, wif0.x); fma2a(af0, hp, wif0.y);
                        fma2a(ag0, hp, wgo0.x); fma2a(ao0, hp, wgo0.y);
                        fma2a(ai1, hp, wif1.x); fma2a(af1, hp, wif1.y);
                        fma2a(ag1, hp, wgo1.x); fma2a(ao1, hp, wgo1.y);
                    }
                }
                float hn0, hn1;
                {
                    float gi = hadd2(ai0) + myXW[j0];
                    float gf = hadd2(af0) + myXW[17 + j0];
                    float gg = hadd2(ag0) + myXW[34 + j0];
                    float go = hadd2(ao0) + myXW[51 + j0];
                    float cn = fmaf(sigmP(gf), c[j0], sigmP(gi) * tanhP(gg));
                    c[j0] = cn; hn0 = sigmP(go) * tanhN(cn);
                }
                {
                    float gi = hadd2(ai1) + myXW[j1];
                    float gf = hadd2(af1) + myXW[17 + j1];
                    float gg = hadd2(ag1) + myXW[34 + j1];
                    float go = hadd2(ao1) + myXW[51 + j1];
                    float cn = fmaf(sigmP(gf), c[j1], sigmP(gi) * tanhP(gg));
                    c[j1] = cn; hn1 = sigmP(go) * tanhN(cn);
                }
                hnew[jj] = pack2(hn0, hn1);
            }
            {   // tail j = 16
                const int j = 16;
                u64 ai, af, ag, ao;
#pragma unroll
                for (int p = 0; p < NP; p++) {
                    ulonglong2 wif = sWhhIF[j * NP + p];
                    ulonglong2 wgo = CHGO(j, p);
                    u64 hp = h[p];
                    if (p == 0) {
                        ai = mul2(hp, wif.x); af = mul2(hp, wif.y);
                        ag = mul2(hp, wgo.x); ao = mul2(hp, wgo.y);
                    } else {
                        fma2a(ai, hp, wif.x); fma2a(af, hp, wif.y);
                        fma2a(ag, hp, wgo.x); fma2a(ao, hp, wgo.y);
                    }
                }
                float gi = hadd2(ai) + myXW[16];
                float gf = hadd2(af) + myXW[33];
                float gg = hadd2(ag) + myXW[50];
                float go = hadd2(ao) + myXW[67];
                float cn = fmaf(sigmP(gf), c[j], sigmP(gi) * tanhP(gg));
                c[j] = cn;
                hnew[8] = pack2(sigmP(go) * tanhN(cn), 1.0f);
            }
        } else {
            // feedback: gates = h@Wcomb ((i,f) LDS, (g,o) LDC; bias in pads)
#pragma unroll
            for (int jj = 0; jj < 8; jj++) {
                const int j0 = 2 * jj, j1 = j0 + 1;
                u64 ai0, af0, ag0, ao0, ai1, af1, ag1, ao1;
#pragma unroll
                for (int p = 0; p < NP; p++) {
                    ulonglong2 wif0 = sWcIF[j0 * NP + p];
                    ulonglong2 wif1 = sWcIF[j1 * NP + p];
                    ulonglong2 wgo0 = CCGO(j0, p);
                    ulonglong2 wgo1 = CCGO(j1, p);
                    u64 hp = h[p];
                    if (p == 0) {
                        ai0 = mul2(hp, wif0.x); af0 = mul2(hp, wif0.y);
                        ag0 = mul2(hp, wgo0.x); ao0 = mul2(hp, wgo0.y);
                        ai1 = mul2(hp, wif1.x); af1 = mul2(hp, wif1.y);
                        ag1 = mul2(hp, wgo1.x); ao1 = mul2(hp, wgo1.y);
                    } else {
                        fma2a(ai0, hp, wif0.x); fma2a(af0, hp, wif0.y);
                        fma2a(ag0, hp, wgo0.x); fma2a(ao0, hp, wgo0.y);
                        fma2a(ai1, hp, wif1.x); fma2a(af1, hp, wif1.y);
                        fma2a(ag1, hp, wgo1.x); fma2a(ao1, hp, wgo1.y);
                    }
                }
                float hn0, hn1;
                {
                    float gi = hadd2(ai0), gf = hadd2(af0), gg = hadd2(ag0), go = hadd2(ao0);
                    float cn = fmaf(sigmP(gf), c[j0], sigmP(gi) * tanhP(gg));
                    c[j0] = cn; hn0 = sigmP(go) * tanhN(cn);
                }
                {
                    float gi = hadd2(ai1), gf = hadd2(af1), gg = hadd2(ag1), go = hadd2(ao1);
                    float cn = fmaf(sigmP(gf), c[j1], sigmP(gi) * tanhP(gg));
                    c[j1] = cn; hn1 = sigmP(go) * tanhN(cn);
                }
                hnew[jj] = pack2(hn0, hn1);
            }
            {   // tail j = 16
                const int j = 16;
                u64 ai, af, ag, ao;
#pragma unroll
                for (int p = 0; p < NP; p++) {
                    ulonglong2 wif = sWcIF[j * NP + p];
                    ulonglong2 wgo = CCGO(j, p);
                    u64 hp = h[p];
                    if (p == 0) {
                        ai = mul2(hp, wif.x); af = mul2(hp, wif.y);
                        ag = mul2(hp, wgo.x); ao = mul2(hp, wgo.y);
                    } else {
                        fma2a(ai, hp, wif.x); fma2a(af, hp, wif.y);
                        fma2a(ag, hp, wgo.x); fma2a(ao, hp, wgo.y);
                    }
                }
                float gi = hadd2(ai), gf = hadd2(af), gg = hadd2(ag), go = hadd2(ao);
                float cn = fmaf(sigmP(gf), c[j], sigmP(gi) * tanhP(gg));
                c[j] = cn;
                hnew[8] = pack2(sigmP(go) * tanhN(cn), 1.0f);
            }
        }
#pragma unroll
        for (int p = 0; p < NP; p++) h[p] = hnew[p];

        if (t >= SLBC) {
            // output GEMV (leaf) + coalesced store via staging
            float o[2 * NP];
#pragma unroll
            for (int ccp = 0; ccp < NP; ccp++) {
                u64 a0, a1;
#pragma unroll
                for (int p = 0; p < NP; p++) {
                    ulonglong2 w = CLIN(ccp, p);
                    if (p == 0) { a0 = mul2(h[0], w.x); a1 = mul2(h[0], w.y); }
                    else        { fma2a(a0, h[p], w.x); fma2a(a1, h[p], w.y); }
                }
                o[2 * ccp] = hadd2(a0); o[2 * ccp + 1] = hadd2(a1);
            }
            int tp = t - SLBC;
            __syncthreads();   // staging buffer free (prior step's readers done)
            u64* myRowW = (u64*)(sS + tid * XROW);
#pragma unroll
            for (int p = 0; p < NP; p++)
                myRowW[p] = pack2(o[2 * p], (2 * p + 1 < DDIM) ? o[2 * p + 1] : 0.0f);
            __syncthreads();
#pragma unroll
            for (int k = 0; k < DDIM; k++) {
                int idx = tid + k * TPB;
                int el = idx / DDIM, d = idx % DDIM;
                og[(long)el * (TOUT * DDIM) + tp * DDIM + d] = sS[el * XROW + d];
            }
        }
    }
}

extern "C" void kernel_launch(void* const* d_in, const int* in_sizes, int n_in,
                              void* d_out, int out_size) {
    const float* x    = (const float*)d_in[0];
    const float* Wih  = (const float*)d_in[1];
    const float* Whh  = (const float*)d_in[2];
    const float* bih  = (const float*)d_in[3];
    const float* bhh  = (const float*)d_in[4];
    const float* Wlin = (const float*)d_in[5];
    const float* blin = (const float*)d_in[6];
    const float* mih  = (const float*)d_in[7];
    const float* mhh  = (const float*)d_in[8];
    float* out = (float*)d_out;

    prep_kernel<<<1, 128>>>(Wih, Whh, bih, bhh, Wlin, blin, mih, mhh);
    void* src = nullptr;
    cudaGetSymbolAddress(&src, g_wbuf);
    cudaMemcpyToSymbolAsync(cbuf, src, CBUF_N * sizeof(ulonglong2), 0,
                            cudaMemcpyDeviceToDevice, 0);
    xw_kernel<<<BSZ / TPB, TPB>>>(x, Wih, mih, bih, bhh);
    lstm_kernel<<<BSZ / TPB, TPB>>>(out);
}